// round 13
// baseline (speedup 1.0000x reference)
#include <cuda_runtime.h>
#include <cstdint>

#define N_ATOMS_MAX 50000
#define N_PAIRS_MAX 800000
#define CDIM 64
#define ROW  (3 * CDIM)   // 192 floats per atom
#define RUN  8            // sorted pairs per 16-thread group

// Static scratch (no allocations allowed).
__device__ float g_agg[N_ATOMS_MAX * ROW];      // 38.4 MB
__device__ int4  g_sorted[N_PAIRS_MAX];         // (j, pair_id, i, 0) sorted by i
__device__ int   g_hist[N_ATOMS_MAX];
__device__ int   g_cursor[N_ATOMS_MAX];

typedef unsigned long long u64;

// ---- packed f32x2 helpers (sm_103a) ---------------------------------------
__device__ __forceinline__ u64 pack2(float a, float b) {
    u64 r; asm("mov.b64 %0, {%1, %2};" : "=l"(r) : "f"(a), "f"(b)); return r;
}
__device__ __forceinline__ void unpack2(u64 v, float& a, float& b) {
    asm("mov.b64 {%0, %1}, %2;" : "=f"(a), "=f"(b) : "l"(v));
}
__device__ __forceinline__ u64 fma2(u64 a, u64 b, u64 c) {
    u64 r; asm("fma.rn.f32x2 %0, %1, %2, %3;" : "=l"(r) : "l"(a), "l"(b), "l"(c)); return r;
}

// ---------------------------------------------------------------------------
// Sort pipeline: histogram -> single-block scan -> scatter
// ---------------------------------------------------------------------------
__global__ void hist_kernel(const int* __restrict__ ind, int* __restrict__ hist,
                            int n_pairs) {
    int p = blockIdx.x * blockDim.x + threadIdx.x;
    if (p < n_pairs) atomicAdd(&hist[ind[2 * p]], 1);
}

// Single-block exclusive scan (shfl warp scan + smem combine), writes cursor.
__global__ void __launch_bounds__(1024) scan_kernel(
    const int* __restrict__ hist, int* __restrict__ cursor, int n)
{
    __shared__ int warp_sum[32];
    __shared__ int warp_off[32];
    __shared__ int carry_s;

    int tid  = threadIdx.x;
    int lane = tid & 31;
    int wid  = tid >> 5;
    if (tid == 0) carry_s = 0;
    __syncthreads();

    for (int base = 0; base < n; base += 1024) {
        int idx = base + tid;
        int v = (idx < n) ? hist[idx] : 0;

        // warp inclusive scan
        int inc = v;
#pragma unroll
        for (int o = 1; o < 32; o <<= 1) {
            int x = __shfl_up_sync(0xFFFFFFFFu, inc, o);
            if (lane >= o) inc += x;
        }
        if (lane == 31) warp_sum[wid] = inc;
        __syncthreads();

        if (wid == 0) {
            int wv = (lane < 32) ? warp_sum[lane] : 0;
            int winc = wv;
#pragma unroll
            for (int o = 1; o < 32; o <<= 1) {
                int x = __shfl_up_sync(0xFFFFFFFFu, winc, o);
                if (lane >= o) winc += x;
            }
            warp_off[lane] = winc - wv;   // exclusive
            if (lane == 31) warp_sum[31] = winc;  // chunk total stashed
        }
        __syncthreads();

        int c = carry_s;
        if (idx < n) cursor[idx] = c + warp_off[wid] + inc - v;
        int chunk_total = warp_sum[31];
        __syncthreads();
        if (tid == 0) carry_s = c + chunk_total;
        __syncthreads();
    }
}

__global__ void scatter_kernel(const int* __restrict__ ind, int* __restrict__ cursor,
                               int4* __restrict__ sorted, int n_pairs) {
    int p = blockIdx.x * blockDim.x + threadIdx.x;
    if (p >= n_pairs) return;
    int2 ij = *reinterpret_cast<const int2*>(ind + 2 * p);
    int pos = atomicAdd(&cursor[ij.x], 1);
    sorted[pos] = make_int4(ij.y, p, ij.x, 0);   // (j, pair_id, i, pad)
}

// ---------------------------------------------------------------------------
// Pair kernel v4: fixed-length runs over the sorted pair list.
// 16-thread group owns RUN=8 consecutive sorted pairs; accumulates in regs,
// red.add.v4 only at segment boundaries (expected ~1.4 flushes per run).
// All 8 run entries preloaded up-front -> independent gather MLP.
// ---------------------------------------------------------------------------
__global__ void __launch_bounds__(256) pair_run_kernel(
    const int4* __restrict__ sorted,
    const float* __restrict__ p3,
    const float* __restrict__ i1,
    const float* __restrict__ d3,
    float* __restrict__ agg,
    int n_pairs)
{
    int t = blockIdx.x * blockDim.x + threadIdx.x;
    int run = t >> 4;
    int base = run * RUN;
    if (base >= n_pairs) return;
    int lane = t & 15;

    // preload entries (independent loads; broadcast across the 16 lanes)
    int4 e[RUN];
#pragma unroll
    for (int k = 0; k < RUN; k++) {
        e[k] = (base + k < n_pairs) ? sorted[base + k] : make_int4(0, 0, -1, 0);
    }

    float4 acc0 = make_float4(0.f, 0.f, 0.f, 0.f);
    float4 acc1 = acc0, acc2 = acc0;
    int cur = e[0].z;

#pragma unroll
    for (int k = 0; k < RUN; k++) {
        int ia = e[k].z;
        if (ia < 0) break;                       // past end (last partial run)
        if (ia != cur) {
            // flush accumulated segment
            float* pa = agg + (size_t)cur * ROW + lane * 4;
            asm volatile("red.global.add.v4.f32 [%0], {%1, %2, %3, %4};"
                         :: "l"(pa), "f"(acc0.x), "f"(acc0.y), "f"(acc0.z), "f"(acc0.w) : "memory");
            asm volatile("red.global.add.v4.f32 [%0], {%1, %2, %3, %4};"
                         :: "l"(pa + CDIM), "f"(acc1.x), "f"(acc1.y), "f"(acc1.z), "f"(acc1.w) : "memory");
            asm volatile("red.global.add.v4.f32 [%0], {%1, %2, %3, %4};"
                         :: "l"(pa + 2 * CDIM), "f"(acc2.x), "f"(acc2.y), "f"(acc2.z), "f"(acc2.w) : "memory");
            acc0 = make_float4(0.f, 0.f, 0.f, 0.f);
            acc1 = acc0; acc2 = acc0;
            cur = ia;
        }
        int j    = e[k].x;
        int pair = e[k].y;

        const float4* pj = reinterpret_cast<const float4*>(p3 + (size_t)j * ROW);
        float4 g = *reinterpret_cast<const float4*>(i1 + (size_t)pair * CDIM + lane * 4);
        float d0 = d3[3 * pair + 0];
        float d1 = d3[3 * pair + 1];
        float d2 = d3[3 * pair + 2];
        float4 v0 = pj[lane];
        float4 v1 = pj[16 + lane];
        float4 v2 = pj[32 + lane];

        acc0.x += (v0.x + d0) * g.x;  acc0.y += (v0.y + d0) * g.y;
        acc0.z += (v0.z + d0) * g.z;  acc0.w += (v0.w + d0) * g.w;
        acc1.x += (v1.x + d1) * g.x;  acc1.y += (v1.y + d1) * g.y;
        acc1.z += (v1.z + d1) * g.z;  acc1.w += (v1.w + d1) * g.w;
        acc2.x += (v2.x + d2) * g.x;  acc2.y += (v2.y + d2) * g.y;
        acc2.z += (v2.z + d2) * g.z;  acc2.w += (v2.w + d2) * g.w;
    }

    // final flush
    {
        float* pa = agg + (size_t)cur * ROW + lane * 4;
        asm volatile("red.global.add.v4.f32 [%0], {%1, %2, %3, %4};"
                     :: "l"(pa), "f"(acc0.x), "f"(acc0.y), "f"(acc0.z), "f"(acc0.w) : "memory");
        asm volatile("red.global.add.v4.f32 [%0], {%1, %2, %3, %4};"
                     :: "l"(pa + CDIM), "f"(acc1.x), "f"(acc1.y), "f"(acc1.z), "f"(acc1.w) : "memory");
        asm volatile("red.global.add.v4.f32 [%0], {%1, %2, %3, %4};"
                     :: "l"(pa + 2 * CDIM), "f"(acc2.x), "f"(acc2.y), "f"(acc2.z), "f"(acc2.w) : "memory");
    }
}

// ---------------------------------------------------------------------------
// Epilogue v3 (unchanged from R8): 16-d x 3-row thread tile, f32x2 FMA.
// ---------------------------------------------------------------------------
#define ATOMS_PER_BLOCK 32

__global__ void __launch_bounds__(128) gemm_kernel(
    const float* __restrict__ agg,
    const float* __restrict__ W,
    float* __restrict__ p3_new,
    float* __restrict__ dotted,
    int n_atoms)
{
    __shared__ __align__(16) float sWT[CDIM][CDIM + 4];           // stride 68
    __shared__ __align__(16) float sA[ATOMS_PER_BLOCK][ROW + 4];  // stride 196

    int tid = threadIdx.x;           // 0..127
    int a0  = blockIdx.x * ATOMS_PER_BLOCK;

    for (int kk = tid; kk < CDIM * CDIM; kk += 128) {
        int d = kk >> 6, c = kk & 63;
        sWT[c][d] = W[kk];
    }
    {
        const float4* src = reinterpret_cast<const float4*>(agg);
        for (int kk = tid; kk < ATOMS_PER_BLOCK * (ROW / 4); kk += 128) {
            int la = kk / (ROW / 4);
            int e4 = kk - la * (ROW / 4);
            int a  = a0 + la;
            float4 v = (a < n_atoms) ? src[(size_t)a * (ROW / 4) + e4]
                                     : make_float4(0.f, 0.f, 0.f, 0.f);
            *reinterpret_cast<float4*>(&sA[la][e4 * 4]) = v;
        }
    }
    __syncthreads();

    int la = tid >> 2;
    int d0 = (tid & 3) * 16;
    int a  = a0 + la;

    u64 acc[3][8];
#pragma unroll
    for (int x = 0; x < 3; x++)
#pragma unroll
        for (int kk = 0; kk < 8; kk++) acc[x][kk] = 0ull;

#pragma unroll 4
    for (int c = 0; c < CDIM; c++) {
        const ulonglong2* wr = reinterpret_cast<const ulonglong2*>(&sWT[c][d0]);
        ulonglong2 w01 = wr[0], w23 = wr[1], w45 = wr[2], w67 = wr[3];

        float av0 = sA[la][c];
        float av1 = sA[la][CDIM + c];
        float av2 = sA[la][2 * CDIM + c];
        u64 aa0 = pack2(av0, av0);
        u64 aa1 = pack2(av1, av1);
        u64 aa2 = pack2(av2, av2);

        acc[0][0] = fma2(aa0, w01.x, acc[0][0]);
        acc[0][1] = fma2(aa0, w01.y, acc[0][1]);
        acc[0][2] = fma2(aa0, w23.x, acc[0][2]);
        acc[0][3] = fma2(aa0, w23.y, acc[0][3]);
        acc[0][4] = fma2(aa0, w45.x, acc[0][4]);
        acc[0][5] = fma2(aa0, w45.y, acc[0][5]);
        acc[0][6] = fma2(aa0, w67.x, acc[0][6]);
        acc[0][7] = fma2(aa0, w67.y, acc[0][7]);

        acc[1][0] = fma2(aa1, w01.x, acc[1][0]);
        acc[1][1] = fma2(aa1, w01.y, acc[1][1]);
        acc[1][2] = fma2(aa1, w23.x, acc[1][2]);
        acc[1][3] = fma2(aa1, w23.y, acc[1][3]);
        acc[1][4] = fma2(aa1, w45.x, acc[1][4]);
        acc[1][5] = fma2(aa1, w45.y, acc[1][5]);
        acc[1][6] = fma2(aa1, w67.x, acc[1][6]);
        acc[1][7] = fma2(aa1, w67.y, acc[1][7]);

        acc[2][0] = fma2(aa2, w01.x, acc[2][0]);
        acc[2][1] = fma2(aa2, w01.y, acc[2][1]);
        acc[2][2] = fma2(aa2, w23.x, acc[2][2]);
        acc[2][3] = fma2(aa2, w23.y, acc[2][3]);
        acc[2][4] = fma2(aa2, w45.x, acc[2][4]);
        acc[2][5] = fma2(aa2, w45.y, acc[2][5]);
        acc[2][6] = fma2(aa2, w67.x, acc[2][6]);
        acc[2][7] = fma2(aa2, w67.y, acc[2][7]);
    }

    if (a >= n_atoms) return;

    float dot[16];
#pragma unroll
    for (int kk = 0; kk < 16; kk++) dot[kk] = 0.f;

#pragma unroll
    for (int x = 0; x < 3; x++) {
        float s[16];
#pragma unroll
        for (int kk = 0; kk < 8; kk++) {
            unpack2(acc[x][kk], s[2 * kk], s[2 * kk + 1]);
            dot[2 * kk]     += s[2 * kk]     * s[2 * kk];
            dot[2 * kk + 1] += s[2 * kk + 1] * s[2 * kk + 1];
        }
        float* out = p3_new + (size_t)a * ROW + x * CDIM + d0;
#pragma unroll
        for (int q = 0; q < 4; q++)
            *reinterpret_cast<float4*>(out + 4 * q) =
                make_float4(s[4 * q], s[4 * q + 1], s[4 * q + 2], s[4 * q + 3]);
    }
    {
        float* out = dotted + (size_t)a * CDIM + d0;
#pragma unroll
        for (int q = 0; q < 4; q++)
            *reinterpret_cast<float4*>(out + 4 * q) =
                make_float4(dot[4 * q], dot[4 * q + 1], dot[4 * q + 2], dot[4 * q + 3]);
    }
}

// ---------------------------------------------------------------------------
// Inputs (metadata order): ind_2 [P,2] i32, p3 [A,3,64] f32, i1 [P,64] f32,
// d3 [P,3] f32, W [64,64] f32.  Output: p3_new [A,3,64] ++ dotted [A,64].
// ---------------------------------------------------------------------------
extern "C" void kernel_launch(void* const* d_in, const int* in_sizes, int n_in,
                              void* d_out, int out_size)
{
    const int*   ind = (const int*)  d_in[0];
    const float* p3  = (const float*)d_in[1];
    const float* i1  = (const float*)d_in[2];
    const float* d3  = (const float*)d_in[3];
    const float* W   = (const float*)d_in[4];

    int n_pairs = in_sizes[0] / 2;
    int n_atoms = in_sizes[1] / ROW;

    float* p3_new = (float*)d_out;
    float* dotted = (float*)d_out + (size_t)n_atoms * ROW;

    float *agg; int *hist, *cursor; int4 *sorted;
    cudaGetSymbolAddress((void**)&agg,    g_agg);
    cudaGetSymbolAddress((void**)&hist,   g_hist);
    cudaGetSymbolAddress((void**)&cursor, g_cursor);
    cudaGetSymbolAddress((void**)&sorted, g_sorted);

    // --- sort pairs by destination atom ---
    cudaMemsetAsync(hist, 0, n_atoms * sizeof(int));
    hist_kernel<<<(n_pairs + 255) / 256, 256>>>(ind, hist, n_pairs);
    scan_kernel<<<1, 1024>>>(hist, cursor, n_atoms);
    scatter_kernel<<<(n_pairs + 255) / 256, 256>>>(ind, cursor, sorted, n_pairs);

    // --- zero accumulator, then run-based accumulation ---
    cudaMemsetAsync(agg, 0, (size_t)n_atoms * ROW * sizeof(float));
    {
        int n_runs = (n_pairs + RUN - 1) / RUN;
        int total  = n_runs * 16;
        pair_run_kernel<<<(total + 255) / 256, 256>>>(sorted, p3, i1, d3, agg, n_pairs);
    }

    // --- epilogue GEMM + dot ---
    {
        int blocks = (n_atoms + ATOMS_PER_BLOCK - 1) / ATOMS_PER_BLOCK;
        gemm_kernel<<<blocks, 128>>>(agg, W, p3_new, dotted, n_atoms);
    }
}

// round 14
// speedup vs baseline: 1.2463x; 1.2463x over previous
#include <cuda_runtime.h>
#include <cstdint>

#define N_ATOMS_MAX 50000
#define CDIM 64
#define ROW  (3 * CDIM)   // 192 floats per atom

// Scratch accumulator (38.4 MB) — static __device__ per harness rules.
__device__ float g_agg[N_ATOMS_MAX * ROW];

typedef unsigned long long u64;

// ---- packed f32x2 helpers (sm_103a) ---------------------------------------
__device__ __forceinline__ u64 pack2(float a, float b) {
    u64 r; asm("mov.b64 %0, {%1, %2};" : "=l"(r) : "f"(a), "f"(b)); return r;
}
__device__ __forceinline__ void unpack2(u64 v, float& a, float& b) {
    asm("mov.b64 {%0, %1}, %2;" : "=f"(a), "=f"(b) : "l"(v));
}
__device__ __forceinline__ u64 fma2(u64 a, u64 b, u64 c) {
    u64 r; asm("fma.rn.f32x2 %0, %1, %2, %3;" : "=l"(r) : "l"(a), "l"(b), "l"(c)); return r;
}

// ---------------------------------------------------------------------------
// Pair kernel (R7 config — measured at the LTS floor, ~114 us).
// 16 threads per pair; each thread owns 4 channels (float4).
//   ix[p,x,c] = (p3[j,x,c] + d3[p,x]) * i1[p,c]  --red.add--> g_agg[i,x,c]
// Streaming-coalesced reads of ind/i1/d3; p3 gather through L2 (p3 fits L2);
// red.global.add.v4.f32 scatter, no return trip.
// ---------------------------------------------------------------------------
__global__ void pair_kernel(const int* __restrict__ ind,
                            const float* __restrict__ p3,
                            const float* __restrict__ i1,
                            const float* __restrict__ d3,
                            float* __restrict__ agg,
                            int n_pairs)
{
    int t = blockIdx.x * blockDim.x + threadIdx.x;
    int pair = t >> 4;
    if (pair >= n_pairs) return;
    int lane = t & 15;                   // channel group: 4 channels each

    int ai = ind[2 * pair + 0];          // destination atom i
    int aj = ind[2 * pair + 1];          // source atom j

    float4 g = *reinterpret_cast<const float4*>(i1 + (size_t)pair * CDIM + lane * 4);

    float dv[3];
    dv[0] = d3[3 * pair + 0];
    dv[1] = d3[3 * pair + 1];
    dv[2] = d3[3 * pair + 2];

    const float4* pj = reinterpret_cast<const float4*>(p3 + (size_t)aj * ROW);
    float4*       pa = reinterpret_cast<float4*>(agg + (size_t)ai * ROW);

#pragma unroll
    for (int x = 0; x < 3; x++) {
        float4 v = pj[x * 16 + lane];
        float dx = dv[x];
        float r0 = (v.x + dx) * g.x;
        float r1 = (v.y + dx) * g.y;
        float r2 = (v.z + dx) * g.z;
        float r3 = (v.w + dx) * g.w;
        asm volatile("red.global.add.v4.f32 [%0], {%1, %2, %3, %4};"
                     :: "l"(pa + x * 16 + lane),
                        "f"(r0), "f"(r1), "f"(r2), "f"(r3)
                     : "memory");
    }
}

// ---------------------------------------------------------------------------
// Epilogue v3: 16-d x 3-row thread tile, f32x2 FMA.
// Block = 128 threads = 32 atoms x 4 d-groups.
// Per c-iter: 4x LDS.128 (w, 16B-aligned stride-68 rows) + 3x LDS.32 (sA,
// stride 196) -> 24 FFMA2.
// ---------------------------------------------------------------------------
#define ATOMS_PER_BLOCK 32

__global__ void __launch_bounds__(128) gemm_kernel(
    const float* __restrict__ agg,
    const float* __restrict__ W,
    float* __restrict__ p3_new,
    float* __restrict__ dotted,
    int n_atoms)
{
    __shared__ __align__(16) float sWT[CDIM][CDIM + 4];           // stride 68
    __shared__ __align__(16) float sA[ATOMS_PER_BLOCK][ROW + 4];  // stride 196

    int tid = threadIdx.x;           // 0..127
    int a0  = blockIdx.x * ATOMS_PER_BLOCK;

    // stage W transposed: sWT[c][d] = W[d*64+c]
    for (int kk = tid; kk < CDIM * CDIM; kk += 128) {
        int d = kk >> 6, c = kk & 63;
        sWT[c][d] = W[kk];
    }
    // stage 32 agg rows (float4)
    {
        const float4* src = reinterpret_cast<const float4*>(agg);
        for (int kk = tid; kk < ATOMS_PER_BLOCK * (ROW / 4); kk += 128) {
            int la = kk / (ROW / 4);
            int e4 = kk - la * (ROW / 4);
            int a  = a0 + la;
            float4 v = (a < n_atoms) ? src[(size_t)a * (ROW / 4) + e4]
                                     : make_float4(0.f, 0.f, 0.f, 0.f);
            *reinterpret_cast<float4*>(&sA[la][e4 * 4]) = v;
        }
    }
    __syncthreads();

    int la = tid >> 2;               // local atom 0..31
    int d0 = (tid & 3) * 16;         // this thread's 16 output channels
    int a  = a0 + la;

    u64 acc[3][8];
#pragma unroll
    for (int x = 0; x < 3; x++)
#pragma unroll
        for (int kk = 0; kk < 8; kk++) acc[x][kk] = 0ull;

#pragma unroll 4
    for (int c = 0; c < CDIM; c++) {
        const ulonglong2* wr = reinterpret_cast<const ulonglong2*>(&sWT[c][d0]);
        ulonglong2 w01 = wr[0], w23 = wr[1], w45 = wr[2], w67 = wr[3];

        float av0 = sA[la][c];
        float av1 = sA[la][CDIM + c];
        float av2 = sA[la][2 * CDIM + c];
        u64 aa0 = pack2(av0, av0);
        u64 aa1 = pack2(av1, av1);
        u64 aa2 = pack2(av2, av2);

        acc[0][0] = fma2(aa0, w01.x, acc[0][0]);
        acc[0][1] = fma2(aa0, w01.y, acc[0][1]);
        acc[0][2] = fma2(aa0, w23.x, acc[0][2]);
        acc[0][3] = fma2(aa0, w23.y, acc[0][3]);
        acc[0][4] = fma2(aa0, w45.x, acc[0][4]);
        acc[0][5] = fma2(aa0, w45.y, acc[0][5]);
        acc[0][6] = fma2(aa0, w67.x, acc[0][6]);
        acc[0][7] = fma2(aa0, w67.y, acc[0][7]);

        acc[1][0] = fma2(aa1, w01.x, acc[1][0]);
        acc[1][1] = fma2(aa1, w01.y, acc[1][1]);
        acc[1][2] = fma2(aa1, w23.x, acc[1][2]);
        acc[1][3] = fma2(aa1, w23.y, acc[1][3]);
        acc[1][4] = fma2(aa1, w45.x, acc[1][4]);
        acc[1][5] = fma2(aa1, w45.y, acc[1][5]);
        acc[1][6] = fma2(aa1, w67.x, acc[1][6]);
        acc[1][7] = fma2(aa1, w67.y, acc[1][7]);

        acc[2][0] = fma2(aa2, w01.x, acc[2][0]);
        acc[2][1] = fma2(aa2, w01.y, acc[2][1]);
        acc[2][2] = fma2(aa2, w23.x, acc[2][2]);
        acc[2][3] = fma2(aa2, w23.y, acc[2][3]);
        acc[2][4] = fma2(aa2, w45.x, acc[2][4]);
        acc[2][5] = fma2(aa2, w45.y, acc[2][5]);
        acc[2][6] = fma2(aa2, w67.x, acc[2][6]);
        acc[2][7] = fma2(aa2, w67.y, acc[2][7]);
    }

    if (a >= n_atoms) return;

    float dot[16];
#pragma unroll
    for (int kk = 0; kk < 16; kk++) dot[kk] = 0.f;

#pragma unroll
    for (int x = 0; x < 3; x++) {
        float s[16];
#pragma unroll
        for (int kk = 0; kk < 8; kk++) {
            unpack2(acc[x][kk], s[2 * kk], s[2 * kk + 1]);
            dot[2 * kk]     += s[2 * kk]     * s[2 * kk];
            dot[2 * kk + 1] += s[2 * kk + 1] * s[2 * kk + 1];
        }
        float* out = p3_new + (size_t)a * ROW + x * CDIM + d0;
#pragma unroll
        for (int q = 0; q < 4; q++)
            *reinterpret_cast<float4*>(out + 4 * q) =
                make_float4(s[4 * q], s[4 * q + 1], s[4 * q + 2], s[4 * q + 3]);
    }
    {
        float* out = dotted + (size_t)a * CDIM + d0;
#pragma unroll
        for (int q = 0; q < 4; q++)
            *reinterpret_cast<float4*>(out + 4 * q) =
                make_float4(dot[4 * q], dot[4 * q + 1], dot[4 * q + 2], dot[4 * q + 3]);
    }
}

// ---------------------------------------------------------------------------
// Inputs (metadata order): ind_2 [P,2] i32, p3 [A,3,64] f32, i1 [P,64] f32,
// d3 [P,3] f32, W [64,64] f32.  Output: p3_new [A,3,64] ++ dotted [A,64].
// ---------------------------------------------------------------------------
extern "C" void kernel_launch(void* const* d_in, const int* in_sizes, int n_in,
                              void* d_out, int out_size)
{
    const int*   ind = (const int*)  d_in[0];
    const float* p3  = (const float*)d_in[1];
    const float* i1  = (const float*)d_in[2];
    const float* d3  = (const float*)d_in[3];
    const float* W   = (const float*)d_in[4];

    int n_pairs = in_sizes[0] / 2;
    int n_atoms = in_sizes[1] / ROW;

    float* p3_new = (float*)d_out;
    float* dotted = (float*)d_out + (size_t)n_atoms * ROW;

    float* agg;
    cudaGetSymbolAddress((void**)&agg, g_agg);

    // 1) zero accumulator
    cudaMemsetAsync(agg, 0, (size_t)n_atoms * ROW * sizeof(float));

    // 2) pair scatter-reduce: 16 threads per pair
    {
        int total = n_pairs * 16;
        int blk = 256;
        pair_kernel<<<(total + blk - 1) / blk, blk>>>(ind, p3, i1, d3, agg, n_pairs);
    }

    // 3) epilogue GEMM + dot
    {
        int blocks = (n_atoms + ATOMS_PER_BLOCK - 1) / ATOMS_PER_BLOCK;
        gemm_kernel<<<blocks, 128>>>(agg, W, p3_new, dotted, n_atoms);
    }
}